// round 6
// baseline (speedup 1.0000x reference)
#include <cuda_runtime.h>
#include <cuda_fp16.h>
#include <cuda_fp8.h>
#include <cstdint>

// ---------------- Problem constants / scratch ----------------
#define MAXN 131072
#define MAXE 2000000
#define GRAPHS 128
#define DIM 64

struct __align__(8) EdgeT { int src; float w; };

__device__ int       g_is64;
__device__ int       g_indeg[MAXN];
__device__ float     g_dinv[MAXN];
__device__ int       g_rowptr[MAXN + 1];
__device__ int       g_cursor[MAXN];
__device__ long long g_look[192];
__device__ EdgeT     g_edges[MAXE];
__device__ uint4     g_x8[MAXN * 4];    // fp8 input features
__device__ uint4     g_h1[MAXN * 4];    // fp8 layer outputs
__device__ uint4     g_h2[MAXN * 4];
__device__ __half    g_W16[3 * DIM * DIM];
__device__ __half    g_bufA[MAXN * DIM];  // fp16 final-layer output for pooling

// ---------------- helpers ----------------
__device__ __forceinline__ int loadIdx(const void* p, long long i) {
    if (g_is64) return (int)((const long long*)p)[i];
    return ((const int*)p)[i];
}

// warp-collective: detect int64 vs int32 from first 32 int64 slots of edge array
__device__ __forceinline__ int detect64(const void* p, int n) {
    const long long* q = (const long long*)p;
    long long v = q[threadIdx.x & 31];
    unsigned ok = __ballot_sync(0xffffffffu, v >= 0 && v < (long long)n);
    return ok == 0xffffffffu;
}

__device__ __forceinline__ float4 fp8quad(const uint8_t* base, int node, int idx16) {
    uint32_t u = *(const uint32_t*)(base + (size_t)node * 64 + idx16 * 4);
    __half2_raw h0 = __nv_cvt_fp8x2_to_halfraw2((unsigned short)(u & 0xffff), __NV_E4M3);
    __half2_raw h1 = __nv_cvt_fp8x2_to_halfraw2((unsigned short)(u >> 16), __NV_E4M3);
    float2 a = __half22float2(*(__half2*)&h0);
    float2 b = __half22float2(*(__half2*)&h1);
    return make_float4(a.x, a.y, b.x, b.y);
}

// ---------------- prep (side stream): quantize x -> fp8, convert W -> fp16 ----------------
__global__ void prep_kernel(const float* __restrict__ x, const float* __restrict__ W1,
                            const float* __restrict__ W2, const float* __restrict__ W3,
                            int n4) {
    int gid = blockIdx.x * blockDim.x + threadIdx.x;
    if (gid < 3072) {
        const float* Ws = (gid < 1024) ? W1 : (gid < 2048 ? W2 : W3);
        int j = gid & 1023;
        float4 v = ((const float4*)Ws)[j];
        __half2 p0 = __floats2half2_rn(v.x, v.y);
        __half2 p1 = __floats2half2_rn(v.z, v.w);
        uint2 u;
        u.x = *(unsigned*)&p0;
        u.y = *(unsigned*)&p1;
        *(uint2*)&g_W16[(gid >> 10) * 4096 + j * 4] = u;
    }
    for (int i = gid; i < n4; i += gridDim.x * blockDim.x) {
        float4 v = ((const float4*)x)[i];
        unsigned short a = __nv_cvt_float2_to_fp8x2(make_float2(v.x, v.y), __NV_SATFINITE, __NV_E4M3);
        unsigned short b = __nv_cvt_float2_to_fp8x2(make_float2(v.z, v.w), __NV_SATFINITE, __NV_E4M3);
        ((uint32_t*)g_x8)[i] = (uint32_t)a | ((uint32_t)b << 16);
    }
}

// ---------------- degree histogram (+dtype detect publish) ----------------
__global__ void deg_kernel(const void* eidx, int E, int n) {
    int is64 = detect64(eidx, n);
    if (blockIdx.x == 0 && threadIdx.x == 0) g_is64 = is64;
    int e = blockIdx.x * blockDim.x + threadIdx.x;
    if (e >= E) return;
    int d = is64 ? (int)((const long long*)eidx)[(long long)E + e]
                 : ((const int*)eidx)[E + e];
    atomicAdd(&g_indeg[d], 1);
}

// ---------------- single-kernel scan with decoupled lookback ----------------
__global__ void scan_kernel(int n, int E) {
    __shared__ int sh[256];
    __shared__ int s_off;
    int bid = blockIdx.x, tid = threadIdx.x;
    int base = bid * 1024 + tid * 4;
    int v[4];
#pragma unroll
    for (int i = 0; i < 4; i++) {
        int idx = base + i;
        v[i] = (idx < n) ? g_indeg[idx] : 0;
        if (idx < n) {
            g_dinv[idx] = rsqrtf((float)(v[i] + 1));  // +1 self-loop
            g_indeg[idx] = 0;                          // re-arm for next launch
        }
    }
    int tsum = v[0] + v[1] + v[2] + v[3];
    sh[tid] = tsum;
    __syncthreads();
    int val = tsum;
    for (int off = 1; off < 256; off <<= 1) {
        int t = (tid >= off) ? sh[tid - off] : 0;
        __syncthreads();
        val += t;
        sh[tid] = val;
        __syncthreads();
    }
    if (tid == 255)
        ((volatile long long*)g_look)[bid] = 0x100000000LL | (unsigned)val;
    int myExcl = val - tsum;
    if (tid < 32) {
        int off = 0;
        for (int j = tid; j < bid; j += 32) {
            long long lv;
            do { lv = ((volatile long long*)g_look)[j]; } while (lv == 0);
            off += (int)(lv & 0xffffffffLL);
        }
#pragma unroll
        for (int s = 16; s > 0; s >>= 1) off += __shfl_down_sync(0xffffffffu, off, s);
        if (tid == 0) s_off = off;
    }
    __syncthreads();
    int run = myExcl + s_off;
#pragma unroll
    for (int i = 0; i < 4; i++) {
        int idx = base + i;
        if (idx < n) {
            g_rowptr[idx] = run;
            g_cursor[idx] = run;
        }
        run += v[i];
    }
    if (bid == 0 && tid == 0) g_rowptr[n] = E;
}

// ---------------- edge scatter into CSR (resets lookback flags) ----------------
__global__ void scatter_kernel(const void* eidx, int E, int n) {
    if (blockIdx.x == 0 && threadIdx.x < 192) g_look[threadIdx.x] = 0;
    int is64 = detect64(eidx, n);
    int e = blockIdx.x * blockDim.x + threadIdx.x;
    if (e >= E) return;
    int s, d;
    if (is64) {
        s = (int)((const long long*)eidx)[e];
        d = (int)((const long long*)eidx)[(long long)E + e];
    } else {
        s = ((const int*)eidx)[e];
        d = ((const int*)eidx)[E + e];
    }
    float w = g_dinv[s] * g_dinv[d];
    int pos = atomicAdd(&g_cursor[d], 1);
    EdgeT t;
    t.src = s;
    t.w = w;
    g_edges[pos] = t;
}

// ---------------- fused layer: h_out = act( (Â h_in) @ W + b ) ----------------
// 512 threads = 16 warps = 16 nodes per block (one m16 MMA tile).
template <bool OUT_HALF>
__global__ void fused_layer_kernel(const uint8_t* __restrict__ in8,
                                   const __half* __restrict__ Wg,
                                   const float* __restrict__ bias,
                                   void* __restrict__ outp, int relu, int n) {
    __shared__ __half Wsh[64 * 72];
    __shared__ __half Xs[16 * 72];
    __shared__ __align__(16) uint8_t Ysh[16 * 64 * (OUT_HALF ? 2 : 1)];
    int tid = threadIdx.x;
    int w = tid >> 5, lane = tid & 31;
    int nb = blockIdx.x * 16;

    // stage W (fp16, 64x64) into smem with 72-stride
    {
        uint4 u = ((const uint4*)Wg)[tid];  // 8 halfs
        int k = tid >> 3, c = (tid & 7) * 8;
        *(uint4*)&Wsh[k * 72 + c] = u;
    }

    // ---- gather phase: warp w aggregates node nb+w ----
    int node = nb + w;
    int idx16 = lane & 15;
    int half_ = lane >> 4;
    float4 acc = make_float4(0.f, 0.f, 0.f, 0.f);
    if (node < n) {
        int start = g_rowptr[node];
        int end = g_rowptr[node + 1];
        float dv = g_dinv[node];
        float ws = dv * dv;
        float4 sv = fp8quad(in8, node, idx16);
        if (half_ == 0) {
            acc.x = ws * sv.x; acc.y = ws * sv.y;
            acc.z = ws * sv.z; acc.w = ws * sv.w;
        }
        int e = start + half_;
        for (; e + 6 < end; e += 8) {
            EdgeT d0 = g_edges[e];
            EdgeT d1 = g_edges[e + 2];
            EdgeT d2 = g_edges[e + 4];
            EdgeT d3 = g_edges[e + 6];
            float4 v0 = fp8quad(in8, d0.src, idx16);
            float4 v1 = fp8quad(in8, d1.src, idx16);
            float4 v2 = fp8quad(in8, d2.src, idx16);
            float4 v3 = fp8quad(in8, d3.src, idx16);
            acc.x += d0.w * v0.x; acc.y += d0.w * v0.y; acc.z += d0.w * v0.z; acc.w += d0.w * v0.w;
            acc.x += d1.w * v1.x; acc.y += d1.w * v1.y; acc.z += d1.w * v1.z; acc.w += d1.w * v1.w;
            acc.x += d2.w * v2.x; acc.y += d2.w * v2.y; acc.z += d2.w * v2.z; acc.w += d2.w * v2.w;
            acc.x += d3.w * v3.x; acc.y += d3.w * v3.y; acc.z += d3.w * v3.z; acc.w += d3.w * v3.w;
        }
        for (; e < end; e += 2) {
            EdgeT d0 = g_edges[e];
            float4 v0 = fp8quad(in8, d0.src, idx16);
            acc.x += d0.w * v0.x; acc.y += d0.w * v0.y;
            acc.z += d0.w * v0.z; acc.w += d0.w * v0.w;
        }
    }
    // combine even/odd halves -> lanes 0..15 hold final 4 dims
    acc.x += __shfl_down_sync(0xffffffffu, acc.x, 16);
    acc.y += __shfl_down_sync(0xffffffffu, acc.y, 16);
    acc.z += __shfl_down_sync(0xffffffffu, acc.z, 16);
    acc.w += __shfl_down_sync(0xffffffffu, acc.w, 16);
    if (lane < 16) {
        __half2 p0 = __floats2half2_rn(acc.x, acc.y);
        __half2 p1 = __floats2half2_rn(acc.z, acc.w);
        uint2 u;
        u.x = *(unsigned*)&p0;
        u.y = *(unsigned*)&p1;
        *(uint2*)&Xs[w * 72 + idx16 * 4] = u;
    }
    __syncthreads();

    // ---- MMA phase: warps 0..7, warp w owns cols [w*8, w*8+8) ----
    if (w < 8) {
        uint32_t A[4][4];
#pragma unroll
        for (int kc = 0; kc < 4; kc++) {
            const __half* ap = &Xs[(lane & 15) * 72 + kc * 16 + (lane >> 4) * 8];
            uint32_t sa = (uint32_t)__cvta_generic_to_shared(ap);
            asm volatile("ldmatrix.sync.aligned.m8n8.x4.shared.b16 {%0,%1,%2,%3}, [%4];"
                         : "=r"(A[kc][0]), "=r"(A[kc][1]), "=r"(A[kc][2]), "=r"(A[kc][3])
                         : "r"(sa));
        }
        float D[4] = {0.f, 0.f, 0.f, 0.f};
        int kq = 2 * (lane & 3);
        int cq = lane >> 2;
#pragma unroll
        for (int kc = 0; kc < 4; kc++) {
            int kr = kc * 16 + kq;
            int col = w * 8 + cq;
            __half2 b0 = __halves2half2(Wsh[kr * 72 + col], Wsh[(kr + 1) * 72 + col]);
            __half2 b1 = __halves2half2(Wsh[(kr + 8) * 72 + col], Wsh[(kr + 9) * 72 + col]);
            uint32_t B0 = *(uint32_t*)&b0;
            uint32_t B1 = *(uint32_t*)&b1;
            asm volatile(
                "mma.sync.aligned.m16n8k16.row.col.f32.f16.f16.f32 "
                "{%0,%1,%2,%3}, {%4,%5,%6,%7}, {%8,%9}, {%0,%1,%2,%3};"
                : "+f"(D[0]), "+f"(D[1]), "+f"(D[2]), "+f"(D[3])
                : "r"(A[kc][0]), "r"(A[kc][1]), "r"(A[kc][2]), "r"(A[kc][3]),
                  "r"(B0), "r"(B1));
        }
        int cb = 2 * (lane & 3);
        int c0 = w * 8 + cb;
        float2 bb = *(const float2*)&bias[c0];
        D[0] += bb.x; D[1] += bb.y; D[2] += bb.x; D[3] += bb.y;
        if (relu) {
#pragma unroll
            for (int j = 0; j < 4; j++) D[j] = fmaxf(D[j], 0.f);
        }
        int r = lane >> 2;
        if (OUT_HALF) {
            __half2 p0 = __floats2half2_rn(D[0], D[1]);
            __half2 p1 = __floats2half2_rn(D[2], D[3]);
            *(__half2*)&((__half*)Ysh)[r * 64 + c0] = p0;
            *(__half2*)&((__half*)Ysh)[(r + 8) * 64 + c0] = p1;
        } else {
            unsigned short p0 = __nv_cvt_float2_to_fp8x2(make_float2(D[0], D[1]), __NV_SATFINITE, __NV_E4M3);
            unsigned short p1 = __nv_cvt_float2_to_fp8x2(make_float2(D[2], D[3]), __NV_SATFINITE, __NV_E4M3);
            *(unsigned short*)&Ysh[r * 64 + c0] = p0;
            *(unsigned short*)&Ysh[(r + 8) * 64 + c0] = p1;
        }
    }
    __syncthreads();

    // ---- coalesced writeback ----
    if (OUT_HALF) {
        if (tid < 128) {
            int r = tid >> 3, q = tid & 7;
            int nd = nb + r;
            if (nd < n)
                ((uint4*)outp)[(size_t)nd * 8 + q] = ((const uint4*)Ysh)[tid];
        }
    } else {
        if (tid < 64) {
            int r = tid >> 2, q = tid & 3;
            int nd = nb + r;
            if (nd < n)
                ((uint4*)outp)[(size_t)nd * 4 + q] = ((const uint4*)Ysh)[tid];
        }
    }
}

// ---------------- fused pool + linear (batch sorted -> contiguous ranges) ----------------
__device__ __forceinline__ int lower_bound_batch(const void* batch, int n, int key) {
    int lo = 0, hi = n;
    while (lo < hi) {
        int mid = (lo + hi) >> 1;
        if (loadIdx(batch, mid) < key) lo = mid + 1;
        else hi = mid;
    }
    return lo;
}

__global__ void poolfinal_kernel(const __half* __restrict__ h, const void* batch,
                                 const float* __restrict__ Wlin, const float* __restrict__ blin,
                                 float* __restrict__ out, int n) {
    int g = blockIdx.x;
    int tid = threadIdx.x;  // 256
    __shared__ int s_lo, s_hi;
    if (tid == 0) s_lo = lower_bound_batch(batch, n, g);
    if (tid == 1) s_hi = lower_bound_batch(batch, n, g + 1);
    __syncthreads();
    int lo = s_lo, hi = s_hi;
    int dim = tid & 63;
    int sub = tid >> 6;
    float acc = 0.f;
    for (int node = lo + sub; node < hi; node += 4)
        acc += __half2float(h[(size_t)node * 64 + dim]);
    __shared__ float red[256];
    __shared__ float mean[64];
    red[tid] = acc;
    __syncthreads();
    if (tid < 64) {
        float s = red[tid] + red[tid + 64] + red[tid + 128] + red[tid + 192];
        float cnt = (float)(hi - lo);
        mean[tid] = s / fmaxf(cnt, 1.0f);
    }
    __syncthreads();
    if (tid < 64) {
        float a = blin[tid];
#pragma unroll
        for (int k = 0; k < 64; k++) a += mean[k] * Wlin[k * 64 + tid];
        out[g * 64 + tid] = a;
    }
}

// ---------------- launch ----------------
extern "C" void kernel_launch(void* const* d_in, const int* in_sizes, int n_in,
                              void* d_out, int out_size) {
    const float* x     = (const float*)d_in[0];
    const void*  eidx  = d_in[1];
    const void*  batch = d_in[2];
    const float* W1 = (const float*)d_in[3];
    const float* b1 = (const float*)d_in[4];
    const float* W2 = (const float*)d_in[5];
    const float* b2 = (const float*)d_in[6];
    const float* W3 = (const float*)d_in[7];
    const float* b3 = (const float*)d_in[8];
    const float* Wlin = (const float*)d_in[9];
    const float* blin = (const float*)d_in[10];
    float* out = (float*)d_out;

    int N = in_sizes[0] / DIM;
    int E = in_sizes[1] / 2;

    uint4 *x8, *h1, *h2;
    __half *bufA, *W16;
    cudaGetSymbolAddress((void**)&x8, g_x8);
    cudaGetSymbolAddress((void**)&h1, g_h1);
    cudaGetSymbolAddress((void**)&h2, g_h2);
    cudaGetSymbolAddress((void**)&bufA, g_bufA);
    cudaGetSymbolAddress((void**)&W16, g_W16);

    static cudaStream_t s2 = nullptr;
    static cudaEvent_t evFork = nullptr, evJoin = nullptr;
    if (!s2) {
        cudaStreamCreateWithFlags(&s2, cudaStreamNonBlocking);
        cudaEventCreateWithFlags(&evFork, cudaEventDisableTiming);
        cudaEventCreateWithFlags(&evJoin, cudaEventDisableTiming);
    }

    int nbScan = (N + 1023) / 1024;
    int nbF = (N + 15) / 16;

    // fork: prep (x quant + W conversion) overlaps the edge-setup chain
    cudaEventRecord(evFork, 0);
    cudaStreamWaitEvent(s2, evFork, 0);
    prep_kernel<<<(N * 16 + 255) / 256, 256, 0, s2>>>(x, W1, W2, W3, N * 16);
    cudaEventRecord(evJoin, s2);

    // edge setup chain
    deg_kernel<<<(E + 255) / 256, 256>>>(eidx, E, N);
    scan_kernel<<<nbScan, 256>>>(N, E);
    scatter_kernel<<<(E + 255) / 256, 256>>>(eidx, E, N);

    cudaStreamWaitEvent(0, evJoin, 0);

    // three fused layers
    fused_layer_kernel<false><<<nbF, 512>>>((const uint8_t*)x8, W16, b1, h1, 1, N);
    fused_layer_kernel<false><<<nbF, 512>>>((const uint8_t*)h1, W16 + 4096, b2, h2, 1, N);
    fused_layer_kernel<true><<<nbF, 512>>>((const uint8_t*)h2, W16 + 8192, b3, bufA, 0, N);

    poolfinal_kernel<<<GRAPHS, 256>>>(bufA, batch, Wlin, blin, out, N);
}

// round 7
// speedup vs baseline: 1.0696x; 1.0696x over previous
#include <cuda_runtime.h>
#include <cuda_fp16.h>
#include <cuda_fp8.h>
#include <cstdint>

// ---------------- Problem constants / scratch ----------------
#define MAXN 131072
#define MAXE 2000000
#define GRAPHS 128
#define DIM 64

__device__ int       g_is64;
__device__ int       g_indeg[MAXN];
__device__ float     g_dinv[MAXN];
__device__ int       g_rowptr[MAXN + 1];
__device__ int       g_cursor[MAXN];
__device__ long long g_look[192];
__device__ int       g_esrc[MAXE];          // edge = src only (4 B)
__device__ uint4     g_p8[MAXN * 4];        // fp8 payload p = dinv * xw
__device__ __half    g_x16[MAXN * DIM];     // fp16 copy of input features
__device__ __half    g_bufA[MAXN * DIM];    // fp16 hidden (single buffer, reused)
__device__ __half    g_W16[3 * DIM * DIM];

// ---------------- helpers ----------------
__device__ __forceinline__ int loadIdx(const void* p, long long i) {
    if (g_is64) return (int)((const long long*)p)[i];
    return ((const int*)p)[i];
}

// warp-collective: detect int64 vs int32 from first 32 int64 slots of edge array
__device__ __forceinline__ int detect64(const void* p, int n) {
    const long long* q = (const long long*)p;
    long long v = q[threadIdx.x & 31];
    unsigned ok = __ballot_sync(0xffffffffu, v >= 0 && v < (long long)n);
    return ok == 0xffffffffu;
}

// ---------------- prep (side stream): x fp32->fp16, W fp32->fp16 ----------------
__global__ void prep_kernel(const float* __restrict__ x, const float* __restrict__ W1,
                            const float* __restrict__ W2, const float* __restrict__ W3,
                            int n4) {
    int gid = blockIdx.x * blockDim.x + threadIdx.x;
    if (gid < 3072) {
        const float* Ws = (gid < 1024) ? W1 : (gid < 2048 ? W2 : W3);
        int j = gid & 1023;
        float4 v = ((const float4*)Ws)[j];
        __half2 p0 = __floats2half2_rn(v.x, v.y);
        __half2 p1 = __floats2half2_rn(v.z, v.w);
        uint2 u;
        u.x = *(unsigned*)&p0;
        u.y = *(unsigned*)&p1;
        *(uint2*)&g_W16[(gid >> 10) * 4096 + j * 4] = u;
    }
    for (int i = gid; i < n4; i += gridDim.x * blockDim.x) {
        float4 v = ((const float4*)x)[i];
        __half2 p0 = __floats2half2_rn(v.x, v.y);
        __half2 p1 = __floats2half2_rn(v.z, v.w);
        uint2 u;
        u.x = *(unsigned*)&p0;
        u.y = *(unsigned*)&p1;
        ((uint2*)g_x16)[i] = u;
    }
}

// ---------------- degree histogram (+dtype detect publish) ----------------
__global__ void deg_kernel(const void* eidx, int E, int n) {
    int is64 = detect64(eidx, n);
    if (blockIdx.x == 0 && threadIdx.x == 0) g_is64 = is64;
    int e = blockIdx.x * blockDim.x + threadIdx.x;
    if (e >= E) return;
    int d = is64 ? (int)((const long long*)eidx)[(long long)E + e]
                 : ((const int*)eidx)[E + e];
    atomicAdd(&g_indeg[d], 1);
}

// ---------------- single-kernel scan with decoupled lookback ----------------
__global__ void scan_kernel(int n, int E) {
    __shared__ int sh[256];
    __shared__ int s_off;
    int bid = blockIdx.x, tid = threadIdx.x;
    int base = bid * 1024 + tid * 4;
    int v[4];
#pragma unroll
    for (int i = 0; i < 4; i++) {
        int idx = base + i;
        v[i] = (idx < n) ? g_indeg[idx] : 0;
        if (idx < n) {
            g_dinv[idx] = rsqrtf((float)(v[i] + 1));  // +1 self-loop
            g_indeg[idx] = 0;                          // re-arm for next launch
        }
    }
    int tsum = v[0] + v[1] + v[2] + v[3];
    sh[tid] = tsum;
    __syncthreads();
    int val = tsum;
    for (int off = 1; off < 256; off <<= 1) {
        int t = (tid >= off) ? sh[tid - off] : 0;
        __syncthreads();
        val += t;
        sh[tid] = val;
        __syncthreads();
    }
    if (tid == 255)
        ((volatile long long*)g_look)[bid] = 0x100000000LL | (unsigned)val;
    int myExcl = val - tsum;
    if (tid < 32) {
        int off = 0;
        for (int j = tid; j < bid; j += 32) {
            long long lv;
            do { lv = ((volatile long long*)g_look)[j]; } while (lv == 0);
            off += (int)(lv & 0xffffffffLL);
        }
#pragma unroll
        for (int s = 16; s > 0; s >>= 1) off += __shfl_down_sync(0xffffffffu, off, s);
        if (tid == 0) s_off = off;
    }
    __syncthreads();
    int run = myExcl + s_off;
#pragma unroll
    for (int i = 0; i < 4; i++) {
        int idx = base + i;
        if (idx < n) {
            g_rowptr[idx] = run;
            g_cursor[idx] = run;
        }
        run += v[i];
    }
    if (bid == 0 && tid == 0) g_rowptr[n] = E;
}

// ---------------- edge scatter into CSR: src index only, no weights ----------------
__global__ void scatter_kernel(const void* eidx, int E, int n) {
    if (blockIdx.x == 0 && threadIdx.x < 192) g_look[threadIdx.x] = 0;
    int is64 = detect64(eidx, n);
    int e = blockIdx.x * blockDim.x + threadIdx.x;
    if (e >= E) return;
    int s, d;
    if (is64) {
        s = (int)((const long long*)eidx)[e];
        d = (int)((const long long*)eidx)[(long long)E + e];
    } else {
        s = ((const int*)eidx)[e];
        d = ((const int*)eidx)[E + e];
    }
    int pos = atomicAdd(&g_cursor[d], 1);
    g_esrc[pos] = s;
}

// ---------------- tensor-core GEMM: P[n,64](fp8) = dinv[row] * (X[n,64] @ W) ----------------
__global__ void gemm_mma_kernel(const __half* __restrict__ X, const __half* __restrict__ Wg,
                                uint4* __restrict__ P, int n) {
    __shared__ __half Wh[64 * 72];
    __shared__ __half Xsh[128 * 72];
    __shared__ float dsh[128];
    __shared__ __align__(16) uint8_t Ysh[128 * 64];
    int tid = threadIdx.x;
    int warp = tid >> 5, lane = tid & 31;
    int nb = blockIdx.x * 128;

    // W fp16 -> smem (stride 72)
    for (int i = tid; i < 512; i += 256) {
        uint4 u = ((const uint4*)Wg)[i];  // 8 halfs
        int k = i >> 3, c = (i & 7) * 8;
        *(uint4*)&Wh[k * 72 + c] = u;
    }
    // X rows -> smem
    for (int i = tid; i < 2048; i += 256) {
        int row = i >> 4, seg = i & 15;
        uint2 u;
        if (nb + row < n) u = ((const uint2*)X)[(size_t)(nb + row) * 16 + seg];
        else { u.x = 0; u.y = 0; }
        *(uint2*)&Xsh[row * 72 + seg * 4] = u;
    }
    if (tid < 128) dsh[tid] = (nb + tid < n) ? g_dinv[nb + tid] : 0.f;
    __syncthreads();

    int r0 = warp * 16;
    uint32_t A[4][4];
#pragma unroll
    for (int kc = 0; kc < 4; kc++) {
        const __half* ap = &Xsh[(r0 + (lane & 15)) * 72 + kc * 16 + (lane >> 4) * 8];
        uint32_t sa = (uint32_t)__cvta_generic_to_shared(ap);
        asm volatile("ldmatrix.sync.aligned.m8n8.x4.shared.b16 {%0,%1,%2,%3}, [%4];"
                     : "=r"(A[kc][0]), "=r"(A[kc][1]), "=r"(A[kc][2]), "=r"(A[kc][3])
                     : "r"(sa));
    }
    float D[8][4];
#pragma unroll
    for (int nc = 0; nc < 8; nc++)
#pragma unroll
        for (int j = 0; j < 4; j++) D[nc][j] = 0.f;

    int kq = 2 * (lane & 3);
    int cq = lane >> 2;
#pragma unroll
    for (int kc = 0; kc < 4; kc++) {
#pragma unroll
        for (int nc = 0; nc < 8; nc++) {
            int kr = kc * 16 + kq;
            int col = nc * 8 + cq;
            __half2 b0 = __halves2half2(Wh[kr * 72 + col], Wh[(kr + 1) * 72 + col]);
            __half2 b1 = __halves2half2(Wh[(kr + 8) * 72 + col], Wh[(kr + 9) * 72 + col]);
            uint32_t B0 = *(uint32_t*)&b0;
            uint32_t B1 = *(uint32_t*)&b1;
            asm volatile(
                "mma.sync.aligned.m16n8k16.row.col.f32.f16.f16.f32 "
                "{%0,%1,%2,%3}, {%4,%5,%6,%7}, {%8,%9}, {%0,%1,%2,%3};"
                : "+f"(D[nc][0]), "+f"(D[nc][1]), "+f"(D[nc][2]), "+f"(D[nc][3])
                : "r"(A[kc][0]), "r"(A[kc][1]), "r"(A[kc][2]), "r"(A[kc][3]),
                  "r"(B0), "r"(B1));
        }
    }
    // epilogue: scale by dinv[row], fp32 -> fp8 e4m3 via smem staging
    int g = lane >> 2;
    int cb = 2 * (lane & 3);
    float dlo = dsh[r0 + g];
    float dhi = dsh[r0 + g + 8];
#pragma unroll
    for (int nc = 0; nc < 8; nc++) {
        float2 lo = make_float2(D[nc][0] * dlo, D[nc][1] * dlo);
        float2 hi = make_float2(D[nc][2] * dhi, D[nc][3] * dhi);
        unsigned short p0 = __nv_cvt_float2_to_fp8x2(lo, __NV_SATFINITE, __NV_E4M3);
        unsigned short p1 = __nv_cvt_float2_to_fp8x2(hi, __NV_SATFINITE, __NV_E4M3);
        *(unsigned short*)&Ysh[(r0 + g) * 64 + nc * 8 + cb] = p0;
        *(unsigned short*)&Ysh[(r0 + g + 8) * 64 + nc * 8 + cb] = p1;
    }
    __syncwarp();
#pragma unroll
    for (int j = 0; j < 2; j++) {
        int idx = j * 32 + lane;
        int row = idx >> 2, q = idx & 3;
        int node = nb + r0 + row;
        if (node < n)
            P[(size_t)node * 4 + q] = ((const uint4*)Ysh)[(r0 + row) * 4 + q];
    }
}

// ---------------- aggregation: out = dinv[dst]*(sum p[src] + p[self]) + b ----------------
__device__ __forceinline__ float2 fp8pair(const uint8_t* base, int node, int lane) {
    unsigned short us = ((const unsigned short*)(base + (size_t)node * 64))[lane];
    __half2_raw hr = __nv_cvt_fp8x2_to_halfraw2(us, __NV_E4M3);
    return __half22float2(*(__half2*)&hr);
}

__global__ void aggregate_kernel(const uint8_t* __restrict__ p8, __half* __restrict__ out,
                                 const float* __restrict__ bias, int relu, int n) {
    int node = (blockIdx.x * blockDim.x + threadIdx.x) >> 5;
    int lane = threadIdx.x & 31;
    if (node >= n) return;
    int start = g_rowptr[node];
    int end = g_rowptr[node + 1];
    float dv = g_dinv[node];
    float2 sv = fp8pair(p8, node, lane);
    float accx = sv.x;
    float accy = sv.y;
    int e = start;
    // 8-deep pipeline: 8 src indices then 8 independent 2B gathers (unweighted sum)
    for (; e + 8 <= end; e += 8) {
        int s[8];
#pragma unroll
        for (int i = 0; i < 8; i++) s[i] = g_esrc[e + i];
        float2 v[8];
#pragma unroll
        for (int i = 0; i < 8; i++) v[i] = fp8pair(p8, s[i], lane);
#pragma unroll
        for (int i = 0; i < 8; i++) {
            accx += v[i].x;
            accy += v[i].y;
        }
    }
    for (; e + 2 <= end; e += 2) {
        int s0 = g_esrc[e], s1 = g_esrc[e + 1];
        float2 v0 = fp8pair(p8, s0, lane);
        float2 v1 = fp8pair(p8, s1, lane);
        accx += v0.x + v1.x;
        accy += v0.y + v1.y;
    }
    if (e < end) {
        float2 v = fp8pair(p8, g_esrc[e], lane);
        accx += v.x;
        accy += v.y;
    }
    float2 b2 = *(const float2*)(bias + lane * 2);
    float ox = dv * accx + b2.x;
    float oy = dv * accy + b2.y;
    if (relu) {
        ox = fmaxf(ox, 0.f);
        oy = fmaxf(oy, 0.f);
    }
    __half2 o = __floats2half2_rn(ox, oy);
    ((__half2*)out)[(size_t)node * 32 + lane] = o;
}

// ---------------- fused pool + linear (batch sorted -> contiguous ranges) ----------------
__device__ __forceinline__ int lower_bound_batch(const void* batch, int n, int key) {
    int lo = 0, hi = n;
    while (lo < hi) {
        int mid = (lo + hi) >> 1;
        if (loadIdx(batch, mid) < key) lo = mid + 1;
        else hi = mid;
    }
    return lo;
}

__global__ void poolfinal_kernel(const __half* __restrict__ h, const void* batch,
                                 const float* __restrict__ Wlin, const float* __restrict__ blin,
                                 float* __restrict__ out, int n) {
    int g = blockIdx.x;
    int tid = threadIdx.x;  // 256
    __shared__ int s_lo, s_hi;
    if (tid == 0) s_lo = lower_bound_batch(batch, n, g);
    if (tid == 1) s_hi = lower_bound_batch(batch, n, g + 1);
    __syncthreads();
    int lo = s_lo, hi = s_hi;
    int dim = tid & 63;
    int sub = tid >> 6;
    float acc = 0.f;
    for (int node = lo + sub; node < hi; node += 4)
        acc += __half2float(h[(size_t)node * 64 + dim]);
    __shared__ float red[256];
    __shared__ float mean[64];
    red[tid] = acc;
    __syncthreads();
    if (tid < 64) {
        float s = red[tid] + red[tid + 64] + red[tid + 128] + red[tid + 192];
        float cnt = (float)(hi - lo);
        mean[tid] = s / fmaxf(cnt, 1.0f);
    }
    __syncthreads();
    if (tid < 64) {
        float a = blin[tid];
#pragma unroll
        for (int k = 0; k < 64; k++) a += mean[k] * Wlin[k * 64 + tid];
        out[g * 64 + tid] = a;
    }
}

// ---------------- launch ----------------
extern "C" void kernel_launch(void* const* d_in, const int* in_sizes, int n_in,
                              void* d_out, int out_size) {
    const float* x     = (const float*)d_in[0];
    const void*  eidx  = d_in[1];
    const void*  batch = d_in[2];
    const float* W1 = (const float*)d_in[3];
    const float* b1 = (const float*)d_in[4];
    const float* W2 = (const float*)d_in[5];
    const float* b2 = (const float*)d_in[6];
    const float* W3 = (const float*)d_in[7];
    const float* b3 = (const float*)d_in[8];
    const float* Wlin = (const float*)d_in[9];
    const float* blin = (const float*)d_in[10];
    float* out = (float*)d_out;

    int N = in_sizes[0] / DIM;
    int E = in_sizes[1] / 2;

    uint4* p8;
    __half *bufA, *x16, *W16;
    cudaGetSymbolAddress((void**)&p8, g_p8);
    cudaGetSymbolAddress((void**)&bufA, g_bufA);
    cudaGetSymbolAddress((void**)&x16, g_x16);
    cudaGetSymbolAddress((void**)&W16, g_W16);
    const uint8_t* p8b = (const uint8_t*)p8;

    static cudaStream_t s2 = nullptr;
    static cudaEvent_t evFork = nullptr, evScan = nullptr, evJoin = nullptr;
    if (!s2) {
        cudaStreamCreateWithFlags(&s2, cudaStreamNonBlocking);
        cudaEventCreateWithFlags(&evFork, cudaEventDisableTiming);
        cudaEventCreateWithFlags(&evScan, cudaEventDisableTiming);
        cudaEventCreateWithFlags(&evJoin, cudaEventDisableTiming);
    }

    int nbScan = (N + 1023) / 1024;
    int gemmBlocks = (N + 127) / 128;
    int aggBlocks = (N * 32 + 255) / 256;

    // side stream: prep (x->fp16, W->fp16), then gemm1 after scan's dinv is ready
    cudaEventRecord(evFork, 0);
    cudaStreamWaitEvent(s2, evFork, 0);
    prep_kernel<<<(N * 16 + 255) / 256, 256, 0, s2>>>(x, W1, W2, W3, N * 16);

    // main: edge setup chain
    deg_kernel<<<(E + 255) / 256, 256>>>(eidx, E, N);
    scan_kernel<<<nbScan, 256>>>(N, E);
    cudaEventRecord(evScan, 0);

    // gemm1 runs on s2 concurrently with scatter (both depend on scan; gemm1 also on prep)
    cudaStreamWaitEvent(s2, evScan, 0);
    gemm_mma_kernel<<<gemmBlocks, 256, 0, s2>>>(x16, W16, p8, N);
    cudaEventRecord(evJoin, s2);

    scatter_kernel<<<(E + 255) / 256, 256>>>(eidx, E, N);
    cudaStreamWaitEvent(0, evJoin, 0);

    // layer 1 aggregate, then layers 2 & 3
    aggregate_kernel<<<aggBlocks, 256>>>(p8b, bufA, b1, 1, N);
    gemm_mma_kernel<<<gemmBlocks, 256>>>(bufA, W16 + 4096, p8, N);
    aggregate_kernel<<<aggBlocks, 256>>>(p8b, bufA, b2, 1, N);
    gemm_mma_kernel<<<gemmBlocks, 256>>>(bufA, W16 + 8192, p8, N);
    aggregate_kernel<<<aggBlocks, 256>>>(p8b, bufA, b3, 0, N);

    poolfinal_kernel<<<GRAPHS, 256>>>(bufA, batch, Wlin, blin, out, N);
}